// round 14
// baseline (speedup 1.0000x reference)
#include <cuda_runtime.h>
#include <cuda_fp16.h>

#define BS    512
#define NN    256
#define NP2   128
#define ROWP  132                 // half2 per row (4 pad) -> 528B stride, conflict-free LDS.128
#define MAXIT 200
#define OMEGA 1.5f

#define OFF_M  0                              // matrix: 256*132*4 = 135168 B (binv tiles overlap at init)
#define OFF_E  (NN * ROWP * 4)                // e double buffer: 2*256*4
#define OFF_R  (OFF_E + 2 * NN * 4)           // red (init reductions): 8*4
#define OFF_Q  (OFF_R + 32)                   // errbuf double buffer: 2*4
#define OFF_F  (OFF_Q + 8)                    // flags: 8*4
#define SMEM_TOTAL (OFF_F + 32)

__device__ __forceinline__ float warp_sum(float v) {
#pragma unroll
    for (int o = 16; o > 0; o >>= 1) v += __shfl_xor_sync(0xffffffffu, v, o);
    return v;
}
__device__ __forceinline__ int ld_acq(const int* p) {
    int v;
    unsigned int a = (unsigned int)__cvta_generic_to_shared((void*)p);
    asm volatile("ld.acquire.cta.shared.b32 %0, [%1];" : "=r"(v) : "r"(a));
    return v;
}
__device__ __forceinline__ void st_rel(int* p, int v) {
    unsigned int a = (unsigned int)__cvta_generic_to_shared(p);
    asm volatile("st.release.cta.shared.b32 [%0], %1;" :: "r"(a), "r"(v));
}

// FMA a 16-half2 coefficient quad against 8 e-values into 4 independent accs.
#define FOLD8(q, e0, e1, A0, A1, A2, A3)                                   \
    do {                                                                   \
        float2 f0 = __half22float2(*reinterpret_cast<__half2*>(&(q).x));   \
        float2 f1 = __half22float2(*reinterpret_cast<__half2*>(&(q).y));   \
        float2 f2 = __half22float2(*reinterpret_cast<__half2*>(&(q).z));   \
        float2 f3 = __half22float2(*reinterpret_cast<__half2*>(&(q).w));   \
        A0 = fmaf(-f0.x, (e0).x, A0); A1 = fmaf(-f0.y, (e0).y, A1);        \
        A2 = fmaf(-f1.x, (e0).z, A2); A3 = fmaf(-f1.y, (e0).w, A3);        \
        A0 = fmaf(-f2.x, (e1).x, A0); A1 = fmaf(-f2.y, (e1).y, A1);        \
        A2 = fmaf(-f3.x, (e1).z, A2); A3 = fmaf(-f3.y, (e1).w, A3);        \
    } while (0)

// ---------------------------------------------------------------------------
// One sweep, SMEM-resident, flag-dataflow, 4-way acc chains:
//   (D+wL)e' = ((1-w)D - wU)e.   Thread i = row i.
// Warps 0-6 release immediately after e_new; warp 7 additionally computes
// ||e'||^2 (folds see all other blocks' values uniformly) -> errbuf[parity].
// ---------------------------------------------------------------------------
__device__ float sweep(const __half2* Mi, const float* e_old, float* e_new,
                       int* flag, float* errbuf, const float* binv,
                       const float* uw, float dc, float& ecur,
                       int i, int wid, int lane, int t) {
    float a0 = dc * ecur, a1 = 0.0f, a2 = 0.0f, a3 = 0.0f;
    // Upper, out-of-block (uniform vector loop over blocks wid+1..7).
    int jpb = 16 * wid + 16;
    const uint4* Mv = reinterpret_cast<const uint4*>(Mi + jpb);
    int nv = (NP2 - jpb) >> 2;
#pragma unroll 4
    for (int v = 0; v < nv; v++) {
        uint4 q = Mv[v];
        float4 e0 = *reinterpret_cast<const float4*>(&e_old[2 * jpb + 8 * v]);
        float4 e1 = *reinterpret_cast<const float4*>(&e_old[2 * jpb + 8 * v + 4]);
        FOLD8(q, e0, e1, a0, a1, a2, a3);
    }
    // Upper, in-block: pre-masked coefficients, unconditional, 4-way.
    {
        const float4* eo = reinterpret_cast<const float4*>(&e_old[32 * wid]);
#pragma unroll
        for (int m = 0; m < 8; m++) {
            float4 e4 = eo[m];
            a0 = fmaf(-uw[4 * m],     e4.x, a0);
            a1 = fmaf(-uw[4 * m + 1], e4.y, a1);
            a2 = fmaf(-uw[4 * m + 2], e4.z, a2);
            a3 = fmaf(-uw[4 * m + 3], e4.w, a3);
        }
    }

    // Lower folds: matrix quads prefetched before the spin; only e-loads wait.
    float esq0 = 0.0f, esq1 = 0.0f;            // warp7 norm accumulation
#pragma unroll 1
    for (int blk = 0; blk < wid; blk++) {
        const uint4* Fv = reinterpret_cast<const uint4*>(Mi + 16 * blk);
        uint4 q0 = Fv[0], q1 = Fv[1], q2 = Fv[2], q3 = Fv[3];
        while (ld_acq(&flag[blk]) < t) { }
        const float4* ev = reinterpret_cast<const float4*>(&e_new[32 * blk]);
        float4 e0 = ev[0], e1 = ev[1], e2 = ev[2], e3 = ev[3];
        float4 e4 = ev[4], e5 = ev[5], e6 = ev[6], e7 = ev[7];
        FOLD8(q0, e0, e1, a0, a1, a2, a3);
        FOLD8(q1, e2, e3, a0, a1, a2, a3);
        FOLD8(q2, e4, e5, a0, a1, a2, a3);
        FOLD8(q3, e6, e7, a0, a1, a2, a3);
        if (wid == 7) {                        // uniform values: free norm acc
            esq0 = fmaf(e0.x, e0.x, esq0); esq1 = fmaf(e0.y, e0.y, esq1);
            esq0 = fmaf(e0.z, e0.z, esq0); esq1 = fmaf(e0.w, e0.w, esq1);
            esq0 = fmaf(e1.x, e1.x, esq0); esq1 = fmaf(e1.y, e1.y, esq1);
            esq0 = fmaf(e1.z, e1.z, esq0); esq1 = fmaf(e1.w, e1.w, esq1);
            esq0 = fmaf(e2.x, e2.x, esq0); esq1 = fmaf(e2.y, e2.y, esq1);
            esq0 = fmaf(e2.z, e2.z, esq0); esq1 = fmaf(e2.w, e2.w, esq1);
            esq0 = fmaf(e3.x, e3.x, esq0); esq1 = fmaf(e3.y, e3.y, esq1);
            esq0 = fmaf(e3.z, e3.z, esq0); esq1 = fmaf(e3.w, e3.w, esq1);
            esq0 = fmaf(e4.x, e4.x, esq0); esq1 = fmaf(e4.y, e4.y, esq1);
            esq0 = fmaf(e4.z, e4.z, esq0); esq1 = fmaf(e4.w, e4.w, esq1);
            esq0 = fmaf(e5.x, e5.x, esq0); esq1 = fmaf(e5.y, e5.y, esq1);
            esq0 = fmaf(e5.z, e5.z, esq0); esq1 = fmaf(e5.w, e5.w, esq1);
            esq0 = fmaf(e6.x, e6.x, esq0); esq1 = fmaf(e6.y, e6.y, esq1);
            esq0 = fmaf(e6.z, e6.z, esq0); esq1 = fmaf(e6.w, e6.w, esq1);
            esq0 = fmaf(e7.x, e7.x, esq0); esq1 = fmaf(e7.y, e7.y, esq1);
            esq0 = fmaf(e7.z, e7.z, esq0); esq1 = fmaf(e7.w, e7.w, esq1);
        }
    }
    float acc = (a0 + a1) + (a2 + a3);

    // Chain-free 32x32 block solve (binv = lane's row of T^{-1}); 2 dep chains.
    float x0 = 0.0f, x1 = 0.0f;
#pragma unroll
    for (int k = 0; k < 32; k += 2) {
        x0 = fmaf(binv[k],     __shfl_sync(0xffffffffu, acc, k),     x0);
        x1 = fmaf(binv[k + 1], __shfl_sync(0xffffffffu, acc, k + 1), x1);
    }
    float x = x0 + x1;
    e_new[i] = x;
    ecur = x;
    __syncwarp();                              // all lanes' e_new visible to lane0
    if (wid < 7) {
        if (lane == 0) st_rel(&flag[wid], t);  // release: e_new visible
    } else {
        float ss = warp_sum(x * x);            // own block's norm part
        if (lane == 0) {
            errbuf[t & 1] = esq0 + esq1 + ss;  // uniform esq across lanes
            st_rel(&flag[7], t);               // release: e_new + errbuf
        }
    }

    // Tail: warp7's release transitively covers all warps' sweep-t stores.
    while (ld_acq(&flag[7]) < t) { }
    return sqrtf(errbuf[t & 1]);
}

// ---------------------------------------------------------------------------
// Single phase: iterate each batch to its OWN convergence, zero-fill tail.
// ---------------------------------------------------------------------------
__global__ void __launch_bounds__(256) k_sor(const float* __restrict__ A,
                                             const float* __restrict__ xsol,
                                             const float* __restrict__ theta,
                                             const float* __restrict__ rtol,
                                             float* __restrict__ out) {
    extern __shared__ char smem_raw[];
    __half2* s_M    = reinterpret_cast<__half2*>(smem_raw + OFF_M);
    float*   eb     = reinterpret_cast<float*>(smem_raw + OFF_E);   // [2][NN]
    float*   red    = reinterpret_cast<float*>(smem_raw + OFF_R);   // [8] init only
    float*   errbuf = reinterpret_cast<float*>(smem_raw + OFF_Q);   // [2]
    int*     flag   = reinterpret_cast<int*>(smem_raw + OFF_F);

    int b = blockIdx.x;
    int i = threadIdx.x, wid = i >> 5, lane = i & 31;
    const float* Ab   = A   + (size_t)b * NN * NN;
    float*       outb = out + (size_t)b * (MAXIT + 1);

    // ---- per-warp 32x32 fp32 diag-block inverse; tiles overlap matrix SMEM.
    float* Tt = reinterpret_cast<float*>(smem_raw + OFF_M) + wid * (32 * 33);
#pragma unroll 4
    for (int k = 0; k < 32; k++) {
        float v = Ab[(size_t)(32 * wid + k) * NN + 32 * wid + lane];
        Tt[k * 33 + lane] = (lane < k) ? OMEGA * v : ((lane == k) ? v : 0.0f);
    }
    __syncwarp();
    float dc = (1.0f - OMEGA) * Tt[lane * 33 + lane];
    float binv[32];                            // row `lane` of T^{-1}
#pragma unroll
    for (int j = 31; j >= 0; j--) {
        float s = (j == lane) ? 1.0f : 0.0f;
#pragma unroll
        for (int k = j + 1; k < 32; k++)
            s = fmaf(-Tt[k * 33 + j], binv[k], s);
        binv[j] = (j <= lane) ? s / Tt[j * 33 + j] : 0.0f;
    }
    __syncthreads();                           // tiles done before matrix load

    // ---- load wA into SMEM as fp16 rows (convert in flight) ----
    {
        int g = i >> 7, c = i & 127;           // 2 rows per pass
        for (int r = 0; r < NN; r += 2) {
            int row = r + g;
            float2 av = *reinterpret_cast<const float2*>(Ab + (size_t)row * NN + 2 * c);
            s_M[row * ROWP + c] = __floats2half2_rn(OMEGA * av.x, OMEGA * av.y);
        }
    }
    if (i < 8) flag[i] = 0;
    const __half2* Mi = s_M + i * ROWP;

    // err0, xtol
    float xv = xsol[b * NN + i];
    float p = warp_sum(xv * xv);
    if (lane == 0) red[wid] = p;
    __syncthreads();
    float xtol = rtol[b] * sqrtf(red[0] + red[1] + red[2] + red[3] +
                                 red[4] + red[5] + red[6] + red[7]);
    __syncthreads();
    float ecur = theta[b * NN + i] - xv;
    eb[i] = ecur;                              // buffer 0 (read by sweep 1)
    float q = warp_sum(ecur * ecur);
    if (lane == 0) red[wid] = q;
    __syncthreads();                           // matrix + flags + e + red ready
    float err = sqrtf(red[0] + red[1] + red[2] + red[3] +
                      red[4] + red[5] + red[6] + red[7]);
    if (i == 0) outb[0] = err;

    // ---- pre-masked in-block upper coefficients (loop-invariant) ----
    float uw[32];
#pragma unroll
    for (int m = 0; m < 16; m++) {
        float2 a = __half22float2(Mi[16 * wid + m]);
        int j0 = 32 * wid + 2 * m;
        uw[2 * m]     = (j0     > i) ? a.x : 0.0f;
        uw[2 * m + 1] = (j0 + 1 > i) ? a.y : 0.0f;
    }

    int t = 0;
    while (err > xtol && t < MAXIT) {          // err CTA-uniform
        t++;
        err = sweep(Mi, eb + ((t & 1) ^ 1) * NN, eb + (t & 1) * NN,
                    flag, errbuf, binv, uw, dc, ecur, i, wid, lane, t);
        if (i == 0) outb[t] = err;
    }
    for (int t2 = t + 1 + i; t2 <= MAXIT; t2 += 256) outb[t2] = 0.0f;
}

extern "C" void kernel_launch(void* const* d_in, const int* in_sizes, int n_in,
                              void* d_out, int out_size) {
    const float* A     = (const float*)d_in[0];
    const float* xsol  = (const float*)d_in[2];
    const float* theta = (const float*)d_in[3];
    const float* rtol  = (const float*)d_in[4];
    float*       out   = (float*)d_out;

    static int attr_done = 0;                  // idempotent host-side attr set
    if (!attr_done) {
        cudaFuncSetAttribute(k_sor, cudaFuncAttributeMaxDynamicSharedMemorySize,
                             SMEM_TOTAL);
        attr_done = 1;
    }
    k_sor<<<BS, 256, SMEM_TOTAL>>>(A, xsol, theta, rtol, out);
}